// round 2
// baseline (speedup 1.0000x reference)
#include <cuda_runtime.h>
#include <cuda_bf16.h>
#include <math.h>

// Problem constants
#define PN 8192
#define PD 1024
#define PH 2048
#define PO 1024
#define PE 8
#define PK 2
#define PNK (PN * PK)          // 16384 routed rows
#define PROWS (PNK + PN)       // + shared expert rows = 24576
#define EPSV 1e-5f

// GEMM tiling
#define BM 128
#define BN 128
#define BKT 16

// ----------------------------------------------------------------------------
// Device scratch (static globals -- no allocation in kernel_launch)
// ----------------------------------------------------------------------------
__device__ int   g_count[PE];
__device__ int   g_cursor[PE];
__device__ int   g_segstart[PE + 2];     // segments 0..7 routed, 8 shared, [9]=end
__device__ int   g_top_e[PN * PK];
__device__ float g_top_w[PN * PK];
__device__ int   g_rowtok[PNK];          // routed row -> token
__device__ float g_roww[PNK];            // routed row -> gate weight
__device__ int   g_tokrow[PN * PK];      // token -> its 2 row slots

__device__ float g_a1[PE * PH], g_c1[PE * PH];
__device__ float g_a2[PE * PH], g_c2[PE * PH];
__device__ float g_sa1[PH], g_sc1[PH], g_sa2[PH], g_sc2[PH];

__device__ float g_h1[(size_t)PROWS * PH];   // 201 MB
__device__ float g_h2[(size_t)PROWS * PH];   // 201 MB
__device__ float g_eo[(size_t)PROWS * PO];   // 100 MB

// ----------------------------------------------------------------------------
// Init / gate / scan / scatter / BN-prep
// ----------------------------------------------------------------------------
__global__ void init_kernel() {
    if (threadIdx.x < PE) g_count[threadIdx.x] = 0;
}

__global__ void gate_kernel(const float* __restrict__ x, const float* __restrict__ Wg) {
    int gwarp = (blockIdx.x * blockDim.x + threadIdx.x) >> 5;
    int lane = threadIdx.x & 31;
    if (gwarp >= PN) return;
    const float* xr = x + (size_t)gwarp * PD;
    double logit[PE];
#pragma unroll
    for (int e = 0; e < PE; e++) {
        const float* wr = Wg + (size_t)e * PD;
        double s = 0.0;
        for (int k = lane; k < PD; k += 32) s += (double)xr[k] * (double)wr[k];
#pragma unroll
        for (int off = 16; off; off >>= 1) s += __shfl_down_sync(0xffffffffu, s, off);
        logit[e] = s;
    }
    if (lane == 0) {
        double mx = logit[0];
#pragma unroll
        for (int e = 1; e < PE; e++) if (logit[e] > mx) mx = logit[e];
        double p[PE];
        double psum = 0.0;
#pragma unroll
        for (int e = 0; e < PE; e++) { p[e] = exp(logit[e] - mx); psum += p[e]; }
#pragma unroll
        for (int e = 0; e < PE; e++) p[e] /= psum;
        // top-2 (ties -> lower index first, matching lax.top_k)
        int i1 = 0;
#pragma unroll
        for (int e = 1; e < PE; e++) if (p[e] > p[i1]) i1 = e;
        int i2 = (i1 == 0) ? 1 : 0;
#pragma unroll
        for (int e = 0; e < PE; e++) if (e != i1 && p[e] > p[i2]) i2 = e;
        float w1 = (float)p[i1], w2 = (float)p[i2];
        float t = w1 + w2 + 1e-20f;
        g_top_e[gwarp * 2 + 0] = i1; g_top_w[gwarp * 2 + 0] = w1 / t;
        g_top_e[gwarp * 2 + 1] = i2; g_top_w[gwarp * 2 + 1] = w2 / t;
        atomicAdd(&g_count[i1], 1);
        atomicAdd(&g_count[i2], 1);
    }
}

__global__ void scan_kernel() {
    if (threadIdx.x == 0 && blockIdx.x == 0) {
        int s = 0;
        for (int e = 0; e < PE; e++) {
            g_segstart[e] = s;
            g_cursor[e] = s;
            s += g_count[e];
        }
        g_segstart[PE] = PNK;          // shared expert segment
        g_segstart[PE + 1] = PROWS;
    }
}

__global__ void scatter_kernel() {
    int n = blockIdx.x * blockDim.x + threadIdx.x;
    if (n >= PN) return;
#pragma unroll
    for (int j = 0; j < PK; j++) {
        int e = g_top_e[n * PK + j];
        int pos = atomicAdd(&g_cursor[e], 1);
        g_rowtok[pos] = n;
        g_roww[pos] = g_top_w[n * PK + j];
        g_tokrow[n * PK + j] = pos;
    }
}

__global__ void prep_bn_kernel(
    const float* __restrict__ g1, const float* __restrict__ be1,
    const float* __restrict__ m1, const float* __restrict__ v1,
    const float* __restrict__ g2, const float* __restrict__ be2,
    const float* __restrict__ m2, const float* __restrict__ v2,
    const float* __restrict__ sg1, const float* __restrict__ sbe1,
    const float* __restrict__ sm1, const float* __restrict__ sv1,
    const float* __restrict__ sg2, const float* __restrict__ sbe2,
    const float* __restrict__ sm2, const float* __restrict__ sv2) {
    int i = blockIdx.x * blockDim.x + threadIdx.x;
    if (i < PE * PH) {
        float a1v = g1[i] * rsqrtf(v1[i] + EPSV);
        g_a1[i] = a1v; g_c1[i] = be1[i] - m1[i] * a1v;
        float a2v = g2[i] * rsqrtf(v2[i] + EPSV);
        g_a2[i] = a2v; g_c2[i] = be2[i] - m2[i] * a2v;
    }
    if (i < PH) {
        float a1v = sg1[i] * rsqrtf(sv1[i] + EPSV);
        g_sa1[i] = a1v; g_sc1[i] = sbe1[i] - sm1[i] * a1v;
        float a2v = sg2[i] * rsqrtf(sv2[i] + EPSV);
        g_sa2[i] = a2v; g_sc2[i] = sbe2[i] - sm2[i] * a2v;
    }
}

// ----------------------------------------------------------------------------
// Tiled SGEMM body.
// A: rows of Abase (LAYER==1: gathered token rows of x; else direct rows).
// W: row-major [cols][KDIM].  Out row stride = OUTN.
// LAYER 1/2 epilogue: bn_a*relu(z+bias)+bn_c ; LAYER 3: weight*sigmoid(z+bias)
// ----------------------------------------------------------------------------
template <int KDIM, int LAYER, int OUTN>
__device__ __forceinline__ void gemm_seg(
    const float* __restrict__ Abase, const float* __restrict__ W,
    const float* __restrict__ bias, const float* __restrict__ bn_a,
    const float* __restrict__ bn_c, float* __restrict__ Out,
    int seg, int m0, int mend, int n0) {

    __shared__ float As[BKT][BM];
    __shared__ float Bs[BKT][BN];

    int tid = threadIdx.x;
    int lk = (tid & 3) * 4;   // 0,4,8,12
    int lm = tid >> 2;        // 0..63

    int mrows = mend - m0;
    long aoff0 = -1, aoff1 = -1;
    if (lm < mrows) {
        int r = m0 + lm;
        long ar = (LAYER == 1) ? (long)((seg < PE) ? g_rowtok[r] : (r - PNK)) : (long)r;
        aoff0 = ar * KDIM;
    }
    if (lm + 64 < mrows) {
        int r = m0 + lm + 64;
        long ar = (LAYER == 1) ? (long)((seg < PE) ? g_rowtok[r] : (r - PNK)) : (long)r;
        aoff1 = ar * KDIM;
    }

    int tm = (tid >> 4) * 8;
    int tn = (tid & 15) * 8;

    float acc[8][8];
#pragma unroll
    for (int i = 0; i < 8; i++)
#pragma unroll
        for (int j = 0; j < 8; j++) acc[i][j] = 0.f;

    const size_t wrow0 = (size_t)(n0 + lm) * KDIM;
    const size_t wrow1 = (size_t)(n0 + lm + 64) * KDIM;

    for (int k0 = 0; k0 < KDIM; k0 += BKT) {
        float4 av0 = make_float4(0.f, 0.f, 0.f, 0.f), av1 = av0;
        if (aoff0 >= 0) av0 = *(const float4*)(Abase + aoff0 + k0 + lk);
        if (aoff1 >= 0) av1 = *(const float4*)(Abase + aoff1 + k0 + lk);
        float4 bv0 = *(const float4*)(W + wrow0 + k0 + lk);
        float4 bv1 = *(const float4*)(W + wrow1 + k0 + lk);

        __syncthreads();
        As[lk + 0][lm] = av0.x; As[lk + 1][lm] = av0.y;
        As[lk + 2][lm] = av0.z; As[lk + 3][lm] = av0.w;
        As[lk + 0][lm + 64] = av1.x; As[lk + 1][lm + 64] = av1.y;
        As[lk + 2][lm + 64] = av1.z; As[lk + 3][lm + 64] = av1.w;
        Bs[lk + 0][lm] = bv0.x; Bs[lk + 1][lm] = bv0.y;
        Bs[lk + 2][lm] = bv0.z; Bs[lk + 3][lm] = bv0.w;
        Bs[lk + 0][lm + 64] = bv1.x; Bs[lk + 1][lm + 64] = bv1.y;
        Bs[lk + 2][lm + 64] = bv1.z; Bs[lk + 3][lm + 64] = bv1.w;
        __syncthreads();

#pragma unroll
        for (int k = 0; k < BKT; k++) {
            float4 a0 = *(const float4*)&As[k][tm];
            float4 a1 = *(const float4*)&As[k][tm + 4];
            float4 b0 = *(const float4*)&Bs[k][tn];
            float4 b1 = *(const float4*)&Bs[k][tn + 4];
            float ar[8] = {a0.x, a0.y, a0.z, a0.w, a1.x, a1.y, a1.z, a1.w};
            float br[8] = {b0.x, b0.y, b0.z, b0.w, b1.x, b1.y, b1.z, b1.w};
#pragma unroll
            for (int i = 0; i < 8; i++)
#pragma unroll
                for (int j = 0; j < 8; j++) acc[i][j] += ar[i] * br[j];
        }
    }

#pragma unroll
    for (int i = 0; i < 8; i++) {
        int r = m0 + tm + i;
        if (r >= mend) continue;
        float* orow = Out + (size_t)r * OUTN;
        float rw = 1.f;
        if (LAYER == 3 && seg < PE) rw = g_roww[r];
#pragma unroll
        for (int j = 0; j < 8; j++) {
            int c = n0 + tn + j;
            float z = acc[i][j] + bias[c];
            if (LAYER == 3) {
                orow[c] = rw * (1.f / (1.f + expf(-z)));
            } else {
                z = fmaxf(z, 0.f);
                orow[c] = bn_a[c] * z + bn_c[c];
            }
        }
    }
}

__global__ __launch_bounds__(256, 2) void layer1_kernel(
    const float* __restrict__ x, const float* __restrict__ W1,
    const float* __restrict__ b1, const float* __restrict__ sW1,
    const float* __restrict__ sb1) {
    int seg = blockIdx.z;
    int mbeg = g_segstart[seg], mend = g_segstart[seg + 1];
    int m0 = mbeg + blockIdx.x * BM;
    if (m0 >= mend) return;
    const float* W  = (seg < PE) ? (W1 + (size_t)seg * PH * PD) : sW1;
    const float* bs = (seg < PE) ? (b1 + (size_t)seg * PH) : sb1;
    const float* a  = (seg < PE) ? (g_a1 + (size_t)seg * PH) : g_sa1;
    const float* c  = (seg < PE) ? (g_c1 + (size_t)seg * PH) : g_sc1;
    gemm_seg<PD, 1, PH>(x, W, bs, a, c, g_h1, seg, m0, mend, blockIdx.y * BN);
}

__global__ __launch_bounds__(256, 2) void layer2_kernel(
    const float* __restrict__ W2, const float* __restrict__ b2,
    const float* __restrict__ sW2, const float* __restrict__ sb2) {
    int seg = blockIdx.z;
    int mbeg = g_segstart[seg], mend = g_segstart[seg + 1];
    int m0 = mbeg + blockIdx.x * BM;
    if (m0 >= mend) return;
    const float* W  = (seg < PE) ? (W2 + (size_t)seg * PH * PH) : sW2;
    const float* bs = (seg < PE) ? (b2 + (size_t)seg * PH) : sb2;
    const float* a  = (seg < PE) ? (g_a2 + (size_t)seg * PH) : g_sa2;
    const float* c  = (seg < PE) ? (g_c2 + (size_t)seg * PH) : g_sc2;
    gemm_seg<PH, 2, PH>(g_h1, W, bs, a, c, g_h2, seg, m0, mend, blockIdx.y * BN);
}

__global__ __launch_bounds__(256, 2) void layer3_kernel(
    const float* __restrict__ W3, const float* __restrict__ b3,
    const float* __restrict__ sW3, const float* __restrict__ sb3) {
    int seg = blockIdx.z;
    int mbeg = g_segstart[seg], mend = g_segstart[seg + 1];
    int m0 = mbeg + blockIdx.x * BM;
    if (m0 >= mend) return;
    const float* W  = (seg < PE) ? (W3 + (size_t)seg * PO * PH) : sW3;
    const float* bs = (seg < PE) ? (b3 + (size_t)seg * PO) : sb3;
    gemm_seg<PH, 3, PO>(g_h2, W, bs, nullptr, nullptr, g_eo, seg, m0, mend,
                        blockIdx.y * BN);
}

__global__ void combine_kernel(float* __restrict__ out) {
    int i = blockIdx.x * blockDim.x + threadIdx.x;
    if (i >= PN * PO) return;
    int n = i >> 10;          // PO = 1024
    int o = i & (PO - 1);
    int r0 = g_tokrow[n * 2 + 0];
    int r1 = g_tokrow[n * 2 + 1];
    out[i] = g_eo[(size_t)r0 * PO + o] + g_eo[(size_t)r1 * PO + o] +
             g_eo[(size_t)(PNK + n) * PO + o];
}

// ----------------------------------------------------------------------------
// Launch
// ----------------------------------------------------------------------------
extern "C" void kernel_launch(void* const* d_in, const int* in_sizes, int n_in,
                              void* d_out, int out_size) {
    const float* x   = (const float*)d_in[0];
    const float* Wg  = (const float*)d_in[1];
    const float* W1  = (const float*)d_in[2];
    const float* b1  = (const float*)d_in[3];
    const float* g1  = (const float*)d_in[4];
    const float* be1 = (const float*)d_in[5];
    const float* m1  = (const float*)d_in[6];
    const float* v1  = (const float*)d_in[7];
    const float* W2  = (const float*)d_in[8];
    const float* b2  = (const float*)d_in[9];
    const float* g2  = (const float*)d_in[10];
    const float* be2 = (const float*)d_in[11];
    const float* m2  = (const float*)d_in[12];
    const float* v2  = (const float*)d_in[13];
    const float* W3  = (const float*)d_in[14];
    const float* b3  = (const float*)d_in[15];
    const float* sW1 = (const float*)d_in[16];
    const float* sb1 = (const float*)d_in[17];
    const float* sg1 = (const float*)d_in[18];
    const float* sbe1= (const float*)d_in[19];
    const float* sm1 = (const float*)d_in[20];
    const float* sv1 = (const float*)d_in[21];
    const float* sW2 = (const float*)d_in[22];
    const float* sb2 = (const float*)d_in[23];
    const float* sg2 = (const float*)d_in[24];
    const float* sbe2= (const float*)d_in[25];
    const float* sm2 = (const float*)d_in[26];
    const float* sv2 = (const float*)d_in[27];
    const float* sW3 = (const float*)d_in[28];
    const float* sb3 = (const float*)d_in[29];
    float* out = (float*)d_out;

    init_kernel<<<1, 32>>>();
    prep_bn_kernel<<<(PE * PH + 255) / 256, 256>>>(
        g1, be1, m1, v1, g2, be2, m2, v2,
        sg1, sbe1, sm1, sv1, sg2, sbe2, sm2, sv2);
    gate_kernel<<<(PN * 32) / 256, 256>>>(x, Wg);
    scan_kernel<<<1, 32>>>();
    scatter_kernel<<<(PN + 255) / 256, 256>>>();

    dim3 grid12(PN / BM, PH / BN, PE + 1);   // (64, 16, 9)
    dim3 grid3(PN / BM, PO / BN, PE + 1);    // (64, 8, 9)
    layer1_kernel<<<grid12, 256>>>(x, W1, b1, sW1, sb1);
    layer2_kernel<<<grid12, 256>>>(W2, b2, sW2, sb2);
    layer3_kernel<<<grid3, 256>>>(W3, b3, sW3, sb3);

    combine_kernel<<<(PN * PO + 255) / 256, 256>>>(out);
}

// round 4
// speedup vs baseline: 2.0760x; 2.0760x over previous
#include <cuda_runtime.h>
#include <cuda_bf16.h>
#include <math.h>
#include <stdint.h>

// Problem constants
#define PN 8192
#define PD 1024
#define PH 2048
#define PO 1024
#define PE 8
#define PK 2
#define PNK (PN * PK)
#define PROWS (PNK + PN)
#define EPSV 1e-5f

// ----------------------------------------------------------------------------
// Device scratch
// ----------------------------------------------------------------------------
__device__ int   g_count[PE];
__device__ int   g_cursor[PE];
__device__ int   g_segstart[PE + 2];
__device__ int   g_top_e[PN * PK];
__device__ float g_top_w[PN * PK];
__device__ int   g_rowtok[PNK];
__device__ float g_roww[PNK];
__device__ int   g_tokrow[PN * PK];

__device__ float g_a1[PE * PH], g_c1[PE * PH];
__device__ float g_a2[PE * PH], g_c2[PE * PH];
__device__ float g_sa1[PH], g_sc1[PH], g_sa2[PH], g_sc2[PH];

// split-bf16 weights
__device__ __nv_bfloat16 g_W1hi[(size_t)PE * PH * PD], g_W1lo[(size_t)PE * PH * PD];
__device__ __nv_bfloat16 g_W2hi[(size_t)PE * PH * PH], g_W2lo[(size_t)PE * PH * PH];
__device__ __nv_bfloat16 g_W3hi[(size_t)PE * PO * PH], g_W3lo[(size_t)PE * PO * PH];
__device__ __nv_bfloat16 g_sW1hi[(size_t)PH * PD], g_sW1lo[(size_t)PH * PD];
__device__ __nv_bfloat16 g_sW2hi[(size_t)PH * PH], g_sW2lo[(size_t)PH * PH];
__device__ __nv_bfloat16 g_sW3hi[(size_t)PO * PH], g_sW3lo[(size_t)PO * PH];

// split-bf16 activations
__device__ __nv_bfloat16 g_xghi[(size_t)PROWS * PD], g_xglo[(size_t)PROWS * PD];
__device__ __nv_bfloat16 g_h1hi[(size_t)PROWS * PH], g_h1lo[(size_t)PROWS * PH];
__device__ __nv_bfloat16 g_h2hi[(size_t)PROWS * PH], g_h2lo[(size_t)PROWS * PH];
__device__ float g_eo[(size_t)PROWS * PO];

// ----------------------------------------------------------------------------
// PTX helpers (base sm_103 target only: cp.async, ldmatrix, mma.sync)
// ----------------------------------------------------------------------------
__device__ __forceinline__ uint32_t s2u(const void* p) {
    uint32_t a;
    asm("{ .reg .u64 t; cvta.to.shared.u64 t, %1; cvt.u32.u64 %0, t; }"
        : "=r"(a) : "l"(p));
    return a;
}
__device__ __forceinline__ void cp16(uint32_t d, const void* s) {
    asm volatile("cp.async.cg.shared.global [%0], [%1], 16;" :: "r"(d), "l"(s));
}
__device__ __forceinline__ void cp_commit() { asm volatile("cp.async.commit_group;"); }
__device__ __forceinline__ void cp_wait1()  { asm volatile("cp.async.wait_group 1;"); }
__device__ __forceinline__ void cp_wait0()  { asm volatile("cp.async.wait_group 0;"); }

__device__ __forceinline__ void ldm4(uint32_t* r, uint32_t addr) {
    asm volatile("ldmatrix.sync.aligned.m8n8.x4.shared.b16 {%0,%1,%2,%3}, [%4];"
                 : "=r"(r[0]), "=r"(r[1]), "=r"(r[2]), "=r"(r[3]) : "r"(addr));
}
__device__ __forceinline__ void mma_bf16(float* d, const uint32_t* a, const uint32_t* b) {
    asm volatile(
        "mma.sync.aligned.m16n8k16.row.col.f32.bf16.bf16.f32 "
        "{%0,%1,%2,%3}, {%4,%5,%6,%7}, {%8,%9}, {%0,%1,%2,%3};"
        : "+f"(d[0]), "+f"(d[1]), "+f"(d[2]), "+f"(d[3])
        : "r"(a[0]), "r"(a[1]), "r"(a[2]), "r"(a[3]), "r"(b[0]), "r"(b[1]));
}

// ----------------------------------------------------------------------------
// Routing / prep kernels (verified in R1/R2)
// ----------------------------------------------------------------------------
__global__ void init_kernel() {
    if (threadIdx.x < PE) g_count[threadIdx.x] = 0;
}

__global__ void gate_kernel(const float* __restrict__ x, const float* __restrict__ Wg) {
    int gwarp = (blockIdx.x * blockDim.x + threadIdx.x) >> 5;
    int lane = threadIdx.x & 31;
    if (gwarp >= PN) return;
    const float* xr = x + (size_t)gwarp * PD;
    double logit[PE];
#pragma unroll
    for (int e = 0; e < PE; e++) {
        const float* wr = Wg + (size_t)e * PD;
        double s = 0.0;
        for (int k = lane; k < PD; k += 32) s += (double)xr[k] * (double)wr[k];
#pragma unroll
        for (int off = 16; off; off >>= 1) s += __shfl_down_sync(0xffffffffu, s, off);
        logit[e] = s;
    }
    if (lane == 0) {
        double mx = logit[0];
#pragma unroll
        for (int e = 1; e < PE; e++) if (logit[e] > mx) mx = logit[e];
        double p[PE];
        double psum = 0.0;
#pragma unroll
        for (int e = 0; e < PE; e++) { p[e] = exp(logit[e] - mx); psum += p[e]; }
#pragma unroll
        for (int e = 0; e < PE; e++) p[e] /= psum;
        int i1 = 0;
#pragma unroll
        for (int e = 1; e < PE; e++) if (p[e] > p[i1]) i1 = e;
        int i2 = (i1 == 0) ? 1 : 0;
#pragma unroll
        for (int e = 0; e < PE; e++) if (e != i1 && p[e] > p[i2]) i2 = e;
        float w1 = (float)p[i1], w2 = (float)p[i2];
        float t = w1 + w2 + 1e-20f;
        g_top_e[gwarp * 2 + 0] = i1; g_top_w[gwarp * 2 + 0] = w1 / t;
        g_top_e[gwarp * 2 + 1] = i2; g_top_w[gwarp * 2 + 1] = w2 / t;
        atomicAdd(&g_count[i1], 1);
        atomicAdd(&g_count[i2], 1);
    }
}

__global__ void scan_kernel() {
    if (threadIdx.x == 0 && blockIdx.x == 0) {
        int s = 0;
        for (int e = 0; e < PE; e++) {
            g_segstart[e] = s;
            g_cursor[e] = s;
            s += g_count[e];
        }
        g_segstart[PE] = PNK;
        g_segstart[PE + 1] = PROWS;
    }
}

__global__ void scatter_kernel() {
    int n = blockIdx.x * blockDim.x + threadIdx.x;
    if (n >= PN) return;
#pragma unroll
    for (int j = 0; j < PK; j++) {
        int e = g_top_e[n * PK + j];
        int pos = atomicAdd(&g_cursor[e], 1);
        g_rowtok[pos] = n;
        g_roww[pos] = g_top_w[n * PK + j];
        g_tokrow[n * PK + j] = pos;
    }
}

__global__ void prep_bn_kernel(
    const float* __restrict__ g1, const float* __restrict__ be1,
    const float* __restrict__ m1, const float* __restrict__ v1,
    const float* __restrict__ g2, const float* __restrict__ be2,
    const float* __restrict__ m2, const float* __restrict__ v2,
    const float* __restrict__ sg1, const float* __restrict__ sbe1,
    const float* __restrict__ sm1, const float* __restrict__ sv1,
    const float* __restrict__ sg2, const float* __restrict__ sbe2,
    const float* __restrict__ sm2, const float* __restrict__ sv2) {
    int i = blockIdx.x * blockDim.x + threadIdx.x;
    if (i < PE * PH) {
        float a1v = g1[i] * rsqrtf(v1[i] + EPSV);
        g_a1[i] = a1v; g_c1[i] = be1[i] - m1[i] * a1v;
        float a2v = g2[i] * rsqrtf(v2[i] + EPSV);
        g_a2[i] = a2v; g_c2[i] = be2[i] - m2[i] * a2v;
    }
    if (i < PH) {
        float a1v = sg1[i] * rsqrtf(sv1[i] + EPSV);
        g_sa1[i] = a1v; g_sc1[i] = sbe1[i] - sm1[i] * a1v;
        float a2v = sg2[i] * rsqrtf(sv2[i] + EPSV);
        g_sa2[i] = a2v; g_sc2[i] = sbe2[i] - sm2[i] * a2v;
    }
}

__global__ void conv_split(const float* __restrict__ s, __nv_bfloat16* __restrict__ hi,
                           __nv_bfloat16* __restrict__ lo, int n) {
    int i = blockIdx.x * 256 + threadIdx.x;
    if (i < n) {
        float v = s[i];
        __nv_bfloat16 h = __float2bfloat16(v);
        hi[i] = h;
        lo[i] = __float2bfloat16(v - __bfloat162float(h));
    }
}

__global__ void gather_x_kernel(const float* __restrict__ x) {
    int row = blockIdx.x;
    int tok = (row < PNK) ? g_rowtok[row] : (row - PNK);
    const float* xr = x + (size_t)tok * PD;
    size_t o = (size_t)row * PD;
    for (int k = threadIdx.x; k < PD; k += 256) {
        float v = xr[k];
        __nv_bfloat16 h = __float2bfloat16(v);
        g_xghi[o + k] = h;
        g_xglo[o + k] = __float2bfloat16(v - __bfloat162float(h));
    }
}

// ----------------------------------------------------------------------------
// mma.sync split-bf16 GEMM.  BM=128, BN=128, BK=32, 8 warps (4M x 2N),
// warp tile 32x64.  SMEM: per stage {Ahi, Alo, Bhi, Blo}, each 128 rows
// x 80 B stride (64 B valid) = 10240 B; 2 stages = 81920 B.
// ----------------------------------------------------------------------------
#define SROWB 80
#define BUFB  10240
#define STGB  40960
#define SMEM_GEMM (2 * STGB)

template <int KDIM, int LAYER, int OUTN>
__global__ __launch_bounds__(256, 1) void gemm_mma(
    const float* __restrict__ bias_r, const float* __restrict__ bias_s) {
    extern __shared__ char smem[];
    const int seg = blockIdx.z;
    const int mbeg = g_segstart[seg], mend = g_segstart[seg + 1];
    const int m0 = mbeg + (int)blockIdx.x * 128;
    if (m0 >= mend) return;
    const int n0 = (int)blockIdx.y * 128;
    const int tid = threadIdx.x;
    const int lane = tid & 31, wid = tid >> 5;
    const int warp_m = wid >> 1, warp_n = wid & 1;   // 4 x 2
    const int mrows = min(128, mend - m0);

    const uint32_t sb = s2u(smem);

    // operand pointers
    const __nv_bfloat16 *Ahi, *Alo, *Bhi, *Blo;
    if (LAYER == 1) {
        Ahi = g_xghi; Alo = g_xglo;
        if (seg < PE) { Bhi = g_W1hi + (size_t)seg * PH * PD; Blo = g_W1lo + (size_t)seg * PH * PD; }
        else          { Bhi = g_sW1hi; Blo = g_sW1lo; }
    } else if (LAYER == 2) {
        Ahi = g_h1hi; Alo = g_h1lo;
        if (seg < PE) { Bhi = g_W2hi + (size_t)seg * PH * PH; Blo = g_W2lo + (size_t)seg * PH * PH; }
        else          { Bhi = g_sW2hi; Blo = g_sW2lo; }
    } else {
        Ahi = g_h2hi; Alo = g_h2lo;
        if (seg < PE) { Bhi = g_W3hi + (size_t)seg * PO * PH; Blo = g_W3lo + (size_t)seg * PO * PH; }
        else          { Bhi = g_sW3hi; Blo = g_sW3lo; }
    }

    auto load_stage = [&](int kk, int st) {
        const uint32_t base = sb + (uint32_t)st * STGB;
#pragma unroll
        for (int j = 0; j < 8; j++) {
            int c = tid + 256 * j;
            int buf = c >> 9;          // 0:Ahi 1:Alo 2:Bhi 3:Blo
            int idx = c & 511;
            int row = idx >> 2;
            int u = idx & 3;
            const __nv_bfloat16* src;
            if (buf < 2) {
                int ra = min(row, mrows - 1);
                src = (buf == 0 ? Ahi : Alo) + (size_t)(m0 + ra) * KDIM + kk + u * 8;
            } else {
                src = (buf == 2 ? Bhi : Blo) + (size_t)(n0 + row) * KDIM + kk + u * 8;
            }
            cp16(base + (uint32_t)(buf * BUFB + row * SROWB + u * 16), src);
        }
        cp_commit();
    };

    float acc[2][8][4];
#pragma unroll
    for (int i = 0; i < 2; i++)
#pragma unroll
        for (int j = 0; j < 8; j++)
#pragma unroll
            for (int q = 0; q < 4; q++) acc[i][j][q] = 0.f;

    constexpr int NIT = KDIM / 32;
    load_stage(0, 0);
    load_stage(32, 1);

    // ldmatrix lane address components
    const int lm = lane >> 3;       // matrix index 0..3
    const int lr = lane & 7;        // row within 8x8

    for (int it = 0; it < NIT; it++) {
        if (it + 1 < NIT) cp_wait1(); else cp_wait0();
        __syncthreads();
        const uint32_t st = sb + (uint32_t)(it & 1) * STGB;

#pragma unroll
        for (int ks = 0; ks < 32; ks += 16) {
            // A fragments: matrices [r0-7,k0-7],[r8-15,k0-7],[r0-7,k8-15],[r8-15,k8-15]
            uint32_t ah[2][4], al[2][4];
#pragma unroll
            for (int mt = 0; mt < 2; mt++) {
                int r = warp_m * 32 + mt * 16 + lr + (lm & 1) * 8;
                int cc = ks + (lm >> 1) * 8;
                uint32_t addr = st + (uint32_t)(r * SROWB + cc * 2);
                ldm4(ah[mt], addr);
                ldm4(al[mt], addr + BUFB);
            }
            // B fragments: matrices [n0-7,k0],[n0-7,k8],[n8-15,k0],[n8-15,k8]
            uint32_t bh[8][2], bl[8][2];
#pragma unroll
            for (int np = 0; np < 4; np++) {
                int r = warp_n * 64 + np * 16 + lr + (lm >> 1) * 8;
                int cc = ks + (lm & 1) * 8;
                uint32_t addr = st + (uint32_t)(2 * BUFB + r * SROWB + cc * 2);
                uint32_t t4[4];
                ldm4(t4, addr);
                bh[2 * np][0] = t4[0]; bh[2 * np][1] = t4[1];
                bh[2 * np + 1][0] = t4[2]; bh[2 * np + 1][1] = t4[3];
                ldm4(t4, addr + BUFB);
                bl[2 * np][0] = t4[0]; bl[2 * np][1] = t4[1];
                bl[2 * np + 1][0] = t4[2]; bl[2 * np + 1][1] = t4[3];
            }
#pragma unroll
            for (int mt = 0; mt < 2; mt++)
#pragma unroll
                for (int nt = 0; nt < 8; nt++) {
                    mma_bf16(acc[mt][nt], ah[mt], bh[nt]);
                    mma_bf16(acc[mt][nt], ah[mt], bl[nt]);
                    mma_bf16(acc[mt][nt], al[mt], bh[nt]);
                }
        }
        __syncthreads();
        if (it + 2 < NIT) load_stage((it + 2) * 32, it & 1);
    }

    // ------------------------------------------------------------------
    // Epilogue.  acc[mt][nt][q]: rows r0 = warp_m*32+mt*16+(lane>>2) (q0,q1),
    // r1 = r0+8 (q2,q3); cols = warp_n*64+nt*8+2*(lane&3)+{0,1}.
    // ------------------------------------------------------------------
    const int tr = lane >> 2, tc = (lane & 3) * 2;
    const float* bias;
    const float* bna = nullptr;
    const float* bnc = nullptr;
    if (LAYER == 1) {
        bias = (seg < PE) ? bias_r + (size_t)seg * PH : bias_s;
        bna  = (seg < PE) ? g_a1 + (size_t)seg * PH : g_sa1;
        bnc  = (seg < PE) ? g_c1 + (size_t)seg * PH : g_sc1;
    } else if (LAYER == 2) {
        bias = (seg < PE) ? bias_r + (size_t)seg * PH : bias_s;
        bna  = (seg < PE) ? g_a2 + (size_t)seg * PH : g_sa2;
        bnc  = (seg < PE) ? g_c2 + (size_t)seg * PH : g_sc2;
    } else {
        bias = (seg < PE) ? bias_r + (size_t)seg * PO : bias_s;
    }

    __nv_bfloat16* Hhi = (LAYER == 1) ? g_h1hi : g_h2hi;
    __nv_bfloat16* Hlo = (LAYER == 1) ? g_h1lo : g_h2lo;

#pragma unroll
    for (int mt = 0; mt < 2; mt++) {
#pragma unroll
        for (int half = 0; half < 2; half++) {
            int rl = warp_m * 32 + mt * 16 + tr + half * 8;
            if (rl >= mrows) continue;
            int r = m0 + rl;
            float rw = 1.f;
            if (LAYER == 3 && seg < PE) rw = g_roww[r];
#pragma unroll
            for (int nt = 0; nt < 8; nt++) {
                int c = n0 + warp_n * 64 + nt * 8 + tc;
                float v0 = acc[mt][nt][half * 2 + 0] + bias[c];
                float v1 = acc[mt][nt][half * 2 + 1] + bias[c + 1];
                if (LAYER < 3) {
                    v0 = bna[c] * fmaxf(v0, 0.f) + bnc[c];
                    v1 = bna[c + 1] * fmaxf(v1, 0.f) + bnc[c + 1];
                    __nv_bfloat16 h0 = __float2bfloat16(v0);
                    __nv_bfloat16 h1 = __float2bfloat16(v1);
                    __nv_bfloat162 hp; hp.x = h0; hp.y = h1;
                    __nv_bfloat162 lp;
                    lp.x = __float2bfloat16(v0 - __bfloat162float(h0));
                    lp.y = __float2bfloat16(v1 - __bfloat162float(h1));
                    *(__nv_bfloat162*)(Hhi + (size_t)r * OUTN + c) = hp;
                    *(__nv_bfloat162*)(Hlo + (size_t)r * OUTN + c) = lp;
                } else {
                    float2 o;
                    o.x = rw * (1.f / (1.f + expf(-v0)));
                    o.y = rw * (1.f / (1.f + expf(-v1)));
                    *(float2*)(g_eo + (size_t)r * PO + c) = o;
                }
            }
        }
    }
}

__global__ void combine_kernel(float* __restrict__ out) {
    int i = blockIdx.x * blockDim.x + threadIdx.x;
    if (i >= PN * PO) return;
    int n = i >> 10;
    int o = i & (PO - 1);
    int r0 = g_tokrow[n * 2 + 0];
    int r1 = g_tokrow[n * 2 + 1];
    out[i] = g_eo[(size_t)r0 * PO + o] + g_eo[(size_t)r1 * PO + o] +
             g_eo[(size_t)(PNK + n) * PO + o];
}

// ----------------------------------------------------------------------------
// Launch
// ----------------------------------------------------------------------------
extern "C" void kernel_launch(void* const* d_in, const int* in_sizes, int n_in,
                              void* d_out, int out_size) {
    const float* x   = (const float*)d_in[0];
    const float* Wg  = (const float*)d_in[1];
    const float* W1  = (const float*)d_in[2];
    const float* b1  = (const float*)d_in[3];
    const float* g1  = (const float*)d_in[4];
    const float* be1 = (const float*)d_in[5];
    const float* m1  = (const float*)d_in[6];
    const float* v1  = (const float*)d_in[7];
    const float* W2  = (const float*)d_in[8];
    const float* b2  = (const float*)d_in[9];
    const float* g2  = (const float*)d_in[10];
    const float* be2 = (const float*)d_in[11];
    const float* m2  = (const float*)d_in[12];
    const float* v2  = (const float*)d_in[13];
    const float* W3  = (const float*)d_in[14];
    const float* b3  = (const float*)d_in[15];
    const float* sW1 = (const float*)d_in[16];
    const float* sb1 = (const float*)d_in[17];
    const float* sg1 = (const float*)d_in[18];
    const float* sbe1= (const float*)d_in[19];
    const float* sm1 = (const float*)d_in[20];
    const float* sv1 = (const float*)d_in[21];
    const float* sW2 = (const float*)d_in[22];
    const float* sb2 = (const float*)d_in[23];
    const float* sg2 = (const float*)d_in[24];
    const float* sbe2= (const float*)d_in[25];
    const float* sm2 = (const float*)d_in[26];
    const float* sv2 = (const float*)d_in[27];
    const float* sW3 = (const float*)d_in[28];
    const float* sb3 = (const float*)d_in[29];
    float* out = (float*)d_out;

    static int smem_set = 0;
    if (!smem_set) {
        cudaFuncSetAttribute(gemm_mma<PD, 1, PH>,
                             cudaFuncAttributeMaxDynamicSharedMemorySize, SMEM_GEMM);
        cudaFuncSetAttribute(gemm_mma<PH, 2, PH>,
                             cudaFuncAttributeMaxDynamicSharedMemorySize, SMEM_GEMM);
        cudaFuncSetAttribute(gemm_mma<PH, 3, PO>,
                             cudaFuncAttributeMaxDynamicSharedMemorySize, SMEM_GEMM);
        smem_set = 1;
    }

    init_kernel<<<1, 32>>>();
    prep_bn_kernel<<<(PE * PH + 255) / 256, 256>>>(
        g1, be1, m1, v1, g2, be2, m2, v2,
        sg1, sbe1, sm1, sv1, sg2, sbe2, sm2, sv2);
    gate_kernel<<<(PN * 32) / 256, 256>>>(x, Wg);
    scan_kernel<<<1, 32>>>();
    scatter_kernel<<<(PN + 255) / 256, 256>>>();

    {
        __nv_bfloat16 *w1h, *w1l, *w2h, *w2l, *w3h, *w3l;
        __nv_bfloat16 *s1h, *s1l, *s2h, *s2l, *s3h, *s3l;
        cudaGetSymbolAddress((void**)&w1h, g_W1hi); cudaGetSymbolAddress((void**)&w1l, g_W1lo);
        cudaGetSymbolAddress((void**)&w2h, g_W2hi); cudaGetSymbolAddress((void**)&w2l, g_W2lo);
        cudaGetSymbolAddress((void**)&w3h, g_W3hi); cudaGetSymbolAddress((void**)&w3l, g_W3lo);
        cudaGetSymbolAddress((void**)&s1h, g_sW1hi); cudaGetSymbolAddress((void**)&s1l, g_sW1lo);
        cudaGetSymbolAddress((void**)&s2h, g_sW2hi); cudaGetSymbolAddress((void**)&s2l, g_sW2lo);
        cudaGetSymbolAddress((void**)&s3h, g_sW3hi); cudaGetSymbolAddress((void**)&s3l, g_sW3lo);
        int n1 = PE * PH * PD, n2 = PE * PH * PH, n3 = PE * PO * PH;
        conv_split<<<(n1 + 255) / 256, 256>>>(W1, w1h, w1l, n1);
        conv_split<<<(n2 + 255) / 256, 256>>>(W2, w2h, w2l, n2);
        conv_split<<<(n3 + 255) / 256, 256>>>(W3, w3h, w3l, n3);
        conv_split<<<(PH * PD + 255) / 256, 256>>>(sW1, s1h, s1l, PH * PD);
        conv_split<<<(PH * PH + 255) / 256, 256>>>(sW2, s2h, s2l, PH * PH);
        conv_split<<<(PO * PH + 255) / 256, 256>>>(sW3, s3h, s3l, PO * PH);
    }

    gather_x_kernel<<<PROWS, 256>>>(x);

    dim3 grid12(PN / 128, PH / 128, PE + 1);   // (64, 16, 9)
    dim3 grid3(PN / 128, PO / 128, PE + 1);    // (64, 8, 9)
    gemm_mma<PD, 1, PH><<<grid12, 256, SMEM_GEMM>>>(b1, sb1);
    gemm_mma<PH, 2, PH><<<grid12, 256, SMEM_GEMM>>>(b2, sb2);
    gemm_mma<PH, 3, PO><<<grid3, 256, SMEM_GEMM>>>(b3, sb3);

    combine_kernel<<<(PN * PO + 255) / 256, 256>>>(out);
}

// round 6
// speedup vs baseline: 2.0885x; 1.0060x over previous
#include <cuda_runtime.h>
#include <cuda_bf16.h>
#include <math.h>
#include <stdint.h>

// Problem constants
#define PN 8192
#define PD 1024
#define PH 2048
#define PO 1024
#define PE 8
#define PK 2
#define PNK (PN * PK)
#define PROWS (PNK + PN)
#define EPSV 1e-5f

// ----------------------------------------------------------------------------
// Device scratch
// ----------------------------------------------------------------------------
__device__ int   g_count[PE];
__device__ int   g_cursor[PE];
__device__ int   g_segstart[PE + 2];
__device__ int   g_top_e[PN * PK];
__device__ float g_top_w[PN * PK];
__device__ int   g_rowtok[PNK];
__device__ float g_roww[PNK];
__device__ int   g_tokrow[PN * PK];

__device__ float g_a1[PE * PH], g_c1[PE * PH];
__device__ float g_a2[PE * PH], g_c2[PE * PH];
__device__ float g_sa1[PH], g_sc1[PH], g_sa2[PH], g_sc2[PH];

// split-bf16 weights
__device__ __nv_bfloat16 g_W1hi[(size_t)PE * PH * PD], g_W1lo[(size_t)PE * PH * PD];
__device__ __nv_bfloat16 g_W2hi[(size_t)PE * PH * PH], g_W2lo[(size_t)PE * PH * PH];
__device__ __nv_bfloat16 g_W3hi[(size_t)PE * PO * PH], g_W3lo[(size_t)PE * PO * PH];
__device__ __nv_bfloat16 g_sW1hi[(size_t)PH * PD], g_sW1lo[(size_t)PH * PD];
__device__ __nv_bfloat16 g_sW2hi[(size_t)PH * PH], g_sW2lo[(size_t)PH * PH];
__device__ __nv_bfloat16 g_sW3hi[(size_t)PO * PH], g_sW3lo[(size_t)PO * PH];

// split-bf16 activations
__device__ __nv_bfloat16 g_xghi[(size_t)PROWS * PD], g_xglo[(size_t)PROWS * PD];
__device__ __nv_bfloat16 g_h1hi[(size_t)PROWS * PH], g_h1lo[(size_t)PROWS * PH];
__device__ __nv_bfloat16 g_h2hi[(size_t)PROWS * PH], g_h2lo[(size_t)PROWS * PH];
__device__ float g_eo[(size_t)PROWS * PO];

// ----------------------------------------------------------------------------
// PTX helpers (base sm_103 target only: cp.async, ldmatrix, mma.sync)
// ----------------------------------------------------------------------------
__device__ __forceinline__ uint32_t s2u(const void* p) {
    uint32_t a;
    asm("{ .reg .u64 t; cvta.to.shared.u64 t, %1; cvt.u32.u64 %0, t; }"
        : "=r"(a) : "l"(p));
    return a;
}
__device__ __forceinline__ void cp16(uint32_t d, const void* s) {
    asm volatile("cp.async.cg.shared.global [%0], [%1], 16;" :: "r"(d), "l"(s));
}
__device__ __forceinline__ void cp_commit() { asm volatile("cp.async.commit_group;"); }
__device__ __forceinline__ void cp_wait1()  { asm volatile("cp.async.wait_group 1;"); }
__device__ __forceinline__ void cp_wait0()  { asm volatile("cp.async.wait_group 0;"); }

__device__ __forceinline__ void ldm4(uint32_t* r, uint32_t addr) {
    asm volatile("ldmatrix.sync.aligned.m8n8.x4.shared.b16 {%0,%1,%2,%3}, [%4];"
                 : "=r"(r[0]), "=r"(r[1]), "=r"(r[2]), "=r"(r[3]) : "r"(addr));
}
__device__ __forceinline__ void mma_bf16(float* d, const uint32_t* a, const uint32_t* b) {
    asm volatile(
        "mma.sync.aligned.m16n8k16.row.col.f32.bf16.bf16.f32 "
        "{%0,%1,%2,%3}, {%4,%5,%6,%7}, {%8,%9}, {%0,%1,%2,%3};"
        : "+f"(d[0]), "+f"(d[1]), "+f"(d[2]), "+f"(d[3])
        : "r"(a[0]), "r"(a[1]), "r"(a[2]), "r"(a[3]), "r"(b[0]), "r"(b[1]));
}

// ----------------------------------------------------------------------------
// Routing / prep kernels
// ----------------------------------------------------------------------------
__global__ void init_kernel() {
    if (threadIdx.x < PE) g_count[threadIdx.x] = 0;
}

__global__ void gate_kernel(const float* __restrict__ x, const float* __restrict__ Wg) {
    int gwarp = (blockIdx.x * blockDim.x + threadIdx.x) >> 5;
    int lane = threadIdx.x & 31;
    if (gwarp >= PN) return;
    const float* xr = x + (size_t)gwarp * PD;
    double logit[PE];
#pragma unroll
    for (int e = 0; e < PE; e++) {
        const float* wr = Wg + (size_t)e * PD;
        double s = 0.0;
        for (int k = lane; k < PD; k += 32) s += (double)xr[k] * (double)wr[k];
#pragma unroll
        for (int off = 16; off; off >>= 1) s += __shfl_down_sync(0xffffffffu, s, off);
        logit[e] = s;
    }
    if (lane == 0) {
        double mx = logit[0];
#pragma unroll
        for (int e = 1; e < PE; e++) if (logit[e] > mx) mx = logit[e];
        double p[PE];
        double psum = 0.0;
#pragma unroll
        for (int e = 0; e < PE; e++) { p[e] = exp(logit[e] - mx); psum += p[e]; }
#pragma unroll
        for (int e = 0; e < PE; e++) p[e] /= psum;
        int i1 = 0;
#pragma unroll
        for (int e = 1; e < PE; e++) if (p[e] > p[i1]) i1 = e;
        int i2 = (i1 == 0) ? 1 : 0;
#pragma unroll
        for (int e = 0; e < PE; e++) if (e != i1 && p[e] > p[i2]) i2 = e;
        float w1 = (float)p[i1], w2 = (float)p[i2];
        float t = w1 + w2 + 1e-20f;
        g_top_e[gwarp * 2 + 0] = i1; g_top_w[gwarp * 2 + 0] = w1 / t;
        g_top_e[gwarp * 2 + 1] = i2; g_top_w[gwarp * 2 + 1] = w2 / t;
        atomicAdd(&g_count[i1], 1);
        atomicAdd(&g_count[i2], 1);
    }
}

__global__ void scan_kernel() {
    if (threadIdx.x == 0 && blockIdx.x == 0) {
        int s = 0;
        for (int e = 0; e < PE; e++) {
            g_segstart[e] = s;
            g_cursor[e] = s;
            s += g_count[e];
        }
        g_segstart[PE] = PNK;
        g_segstart[PE + 1] = PROWS;
    }
}

__global__ void scatter_kernel() {
    int n = blockIdx.x * blockDim.x + threadIdx.x;
    if (n >= PN) return;
#pragma unroll
    for (int j = 0; j < PK; j++) {
        int e = g_top_e[n * PK + j];
        int pos = atomicAdd(&g_cursor[e], 1);
        g_rowtok[pos] = n;
        g_roww[pos] = g_top_w[n * PK + j];
        g_tokrow[n * PK + j] = pos;
    }
}

__global__ void prep_bn_kernel(
    const float* __restrict__ g1, const float* __restrict__ be1,
    const float* __restrict__ m1, const float* __restrict__ v1,
    const float* __restrict__ g2, const float* __restrict__ be2,
    const float* __restrict__ m2, const float* __restrict__ v2,
    const float* __restrict__ sg1, const float* __restrict__ sbe1,
    const float* __restrict__ sm1, const float* __restrict__ sv1,
    const float* __restrict__ sg2, const float* __restrict__ sbe2,
    const float* __restrict__ sm2, const float* __restrict__ sv2) {
    int i = blockIdx.x * blockDim.x + threadIdx.x;
    if (i < PE * PH) {
        float a1v = g1[i] * rsqrtf(v1[i] + EPSV);
        g_a1[i] = a1v; g_c1[i] = be1[i] - m1[i] * a1v;
        float a2v = g2[i] * rsqrtf(v2[i] + EPSV);
        g_a2[i] = a2v; g_c2[i] = be2[i] - m2[i] * a2v;
    }
    if (i < PH) {
        float a1v = sg1[i] * rsqrtf(sv1[i] + EPSV);
        g_sa1[i] = a1v; g_sc1[i] = sbe1[i] - sm1[i] * a1v;
        float a2v = sg2[i] * rsqrtf(sv2[i] + EPSV);
        g_sa2[i] = a2v; g_sc2[i] = sbe2[i] - sm2[i] * a2v;
    }
}

__global__ void conv_split(const float* __restrict__ s, __nv_bfloat16* __restrict__ hi,
                           __nv_bfloat16* __restrict__ lo, int n) {
    int i = blockIdx.x * 256 + threadIdx.x;
    if (i < n) {
        float v = s[i];
        __nv_bfloat16 h = __float2bfloat16(v);
        hi[i] = h;
        lo[i] = __float2bfloat16(v - __bfloat162float(h));
    }
}

__global__ void gather_x_kernel(const float* __restrict__ x) {
    int row = blockIdx.x;
    int tok = (row < PNK) ? g_rowtok[row] : (row - PNK);
    const float* xr = x + (size_t)tok * PD;
    size_t o = (size_t)row * PD;
    for (int k = threadIdx.x; k < PD; k += 256) {
        float v = xr[k];
        __nv_bfloat16 h = __float2bfloat16(v);
        g_xghi[o + k] = h;
        g_xglo[o + k] = __float2bfloat16(v - __bfloat162float(h));
    }
}

// ----------------------------------------------------------------------------
// mma.sync split-bf16 GEMM.  BM=128, BN=128, BK=32, 8 warps (4M x 2N),
// warp tile 32x64.  3-stage cp.async pipeline, one barrier per k-iter.
// SMEM per stage: {Ahi, Alo, Bhi, Blo}, 128 rows x 80 B stride = 10240 B
// each -> 40960 B / stage; 3 stages = 122880 B.
// ----------------------------------------------------------------------------
#define SROWB 80
#define BUFB  10240
#define STGB  40960
#define NSTG  3
#define SMEM_GEMM (NSTG * STGB)

template <int KDIM, int LAYER, int OUTN>
__global__ __launch_bounds__(256, 1) void gemm_mma(
    const float* __restrict__ bias_r, const float* __restrict__ bias_s) {
    extern __shared__ char smem[];
    const int seg = blockIdx.z;
    const int mbeg = g_segstart[seg], mend = g_segstart[seg + 1];
    const int m0 = mbeg + (int)blockIdx.x * 128;
    if (m0 >= mend) return;
    const int n0 = (int)blockIdx.y * 128;
    const int tid = threadIdx.x;
    const int lane = tid & 31, wid = tid >> 5;
    const int warp_m = wid >> 1, warp_n = wid & 1;   // 4 x 2
    const int mrows = min(128, mend - m0);

    const uint32_t sb = s2u(smem);

    // operand pointers
    const __nv_bfloat16 *Ahi, *Alo, *Bhi, *Blo;
    if (LAYER == 1) {
        Ahi = g_xghi; Alo = g_xglo;
        if (seg < PE) { Bhi = g_W1hi + (size_t)seg * PH * PD; Blo = g_W1lo + (size_t)seg * PH * PD; }
        else          { Bhi = g_sW1hi; Blo = g_sW1lo; }
    } else if (LAYER == 2) {
        Ahi = g_h1hi; Alo = g_h1lo;
        if (seg < PE) { Bhi = g_W2hi + (size_t)seg * PH * PH; Blo = g_W2lo + (size_t)seg * PH * PH; }
        else          { Bhi = g_sW2hi; Blo = g_sW2lo; }
    } else {
        Ahi = g_h2hi; Alo = g_h2lo;
        if (seg < PE) { Bhi = g_W3hi + (size_t)seg * PO * PH; Blo = g_W3lo + (size_t)seg * PO * PH; }
        else          { Bhi = g_sW3hi; Blo = g_sW3lo; }
    }

    auto load_stage = [&](int kk, int st) {
        const uint32_t base = sb + (uint32_t)st * STGB;
#pragma unroll
        for (int j = 0; j < 8; j++) {
            int c = tid + 256 * j;
            int buf = c >> 9;          // 0:Ahi 1:Alo 2:Bhi 3:Blo
            int idx = c & 511;
            int row = idx >> 2;
            int u = idx & 3;
            const __nv_bfloat16* src;
            if (buf < 2) {
                int ra = min(row, mrows - 1);
                src = (buf == 0 ? Ahi : Alo) + (size_t)(m0 + ra) * KDIM + kk + u * 8;
            } else {
                src = (buf == 2 ? Bhi : Blo) + (size_t)(n0 + row) * KDIM + kk + u * 8;
            }
            cp16(base + (uint32_t)(buf * BUFB + row * SROWB + u * 16), src);
        }
        cp_commit();
    };

    float acc[2][8][4];
#pragma unroll
    for (int i = 0; i < 2; i++)
#pragma unroll
        for (int j = 0; j < 8; j++)
#pragma unroll
            for (int q = 0; q < 4; q++) acc[i][j][q] = 0.f;

    constexpr int NIT = KDIM / 32;
    load_stage(0, 0);
    load_stage(32, 1);

    const int lm = lane >> 3;       // ldmatrix matrix index 0..3
    const int lr = lane & 7;        // row within 8x8

    for (int it = 0; it < NIT; it++) {
        if (it + 1 < NIT) cp_wait1(); else cp_wait0();
        __syncthreads();
        // prefetch stage it+2 into buffer (it+2)%3 (consumed at it-1; barrier
        // above guarantees all warps are done with it)
        if (it + 2 < NIT) load_stage((it + 2) * 32, (it + 2) % NSTG);

        const uint32_t st = sb + (uint32_t)(it % NSTG) * STGB;

#pragma unroll
        for (int ks = 0; ks < 32; ks += 16) {
            uint32_t ah[2][4], al[2][4];
#pragma unroll
            for (int mt = 0; mt < 2; mt++) {
                int r = warp_m * 32 + mt * 16 + lr + (lm & 1) * 8;
                int cc = ks + (lm >> 1) * 8;
                uint32_t addr = st + (uint32_t)(r * SROWB + cc * 2);
                ldm4(ah[mt], addr);
                ldm4(al[mt], addr + BUFB);
            }
            uint32_t bh[8][2], bl[8][2];
#pragma unroll
            for (int np = 0; np < 4; np++) {
                int r = warp_n * 64 + np * 16 + lr + (lm >> 1) * 8;
                int cc = ks + (lm & 1) * 8;
                uint32_t addr = st + (uint32_t)(2 * BUFB + r * SROWB + cc * 2);
                uint32_t t4[4];
                ldm4(t4, addr);
                bh[2 * np][0] = t4[0]; bh[2 * np][1] = t4[1];
                bh[2 * np + 1][0] = t4[2]; bh[2 * np + 1][1] = t4[3];
                ldm4(t4, addr + BUFB);
                bl[2 * np][0] = t4[0]; bl[2 * np][1] = t4[1];
                bl[2 * np + 1][0] = t4[2]; bl[2 * np + 1][1] = t4[3];
            }
            // Interleaved product order: each accumulator is revisited at
            // distance 16 HMMAs -> no RAW stall on the tensor pipe.
#pragma unroll
            for (int nt = 0; nt < 8; nt++) mma_bf16(acc[0][nt], ah[0], bh[nt]);
#pragma unroll
            for (int nt = 0; nt < 8; nt++) mma_bf16(acc[1][nt], ah[1], bh[nt]);
#pragma unroll
            for (int nt = 0; nt < 8; nt++) mma_bf16(acc[0][nt], ah[0], bl[nt]);
#pragma unroll
            for (int nt = 0; nt < 8; nt++) mma_bf16(acc[1][nt], ah[1], bl[nt]);
#pragma unroll
            for (int nt = 0; nt < 8; nt++) mma_bf16(acc[0][nt], al[0], bh[nt]);
#pragma unroll
            for (int nt = 0; nt < 8; nt++) mma_bf16(acc[1][nt], al[1], bh[nt]);
        }
    }

    // ------------------------------------------------------------------
    // Epilogue
    // ------------------------------------------------------------------
    const int tr = lane >> 2, tc = (lane & 3) * 2;
    const float* bias;
    const float* bna = nullptr;
    const float* bnc = nullptr;
    if (LAYER == 1) {
        bias = (seg < PE) ? bias_r + (size_t)seg * PH : bias_s;
        bna  = (seg < PE) ? g_a1 + (size_t)seg * PH : g_sa1;
        bnc  = (seg < PE) ? g_c1 + (size_t)seg * PH : g_sc1;
    } else if (LAYER == 2) {
        bias = (seg < PE) ? bias_r + (size_t)seg * PH : bias_s;
        bna  = (seg < PE) ? g_a2 + (size_t)seg * PH : g_sa2;
        bnc  = (seg < PE) ? g_c2 + (size_t)seg * PH : g_sc2;
    } else {
        bias = (seg < PE) ? bias_r + (size_t)seg * PO : bias_s;
    }

    __nv_bfloat16* Hhi = (LAYER == 1) ? g_h1hi : g_h2hi;
    __nv_bfloat16* Hlo = (LAYER == 1) ? g_h1lo : g_h2lo;

#pragma unroll
    for (int mt = 0; mt < 2; mt++) {
#pragma unroll
        for (int half = 0; half < 2; half++) {
            int rl = warp_m * 32 + mt * 16 + tr + half * 8;
            if (rl >= mrows) continue;
            int r = m0 + rl;
            float rw = 1.f;
            if (LAYER == 3 && seg < PE) rw = g_roww[r];
#pragma unroll
            for (int nt = 0; nt < 8; nt++) {
                int c = n0 + warp_n * 64 + nt * 8 + tc;
                float v0 = acc[mt][nt][half * 2 + 0] + bias[c];
                float v1 = acc[mt][nt][half * 2 + 1] + bias[c + 1];
                if (LAYER < 3) {
                    v0 = bna[c] * fmaxf(v0, 0.f) + bnc[c];
                    v1 = bna[c + 1] * fmaxf(v1, 0.f) + bnc[c + 1];
                    __nv_bfloat16 h0 = __float2bfloat16(v0);
                    __nv_bfloat16 h1 = __float2bfloat16(v1);
                    __nv_bfloat162 hp; hp.x = h0; hp.y = h1;
                    __nv_bfloat162 lp;
                    lp.x = __float2bfloat16(v0 - __bfloat162float(h0));
                    lp.y = __float2bfloat16(v1 - __bfloat162float(h1));
                    *(__nv_bfloat162*)(Hhi + (size_t)r * OUTN + c) = hp;
                    *(__nv_bfloat162*)(Hlo + (size_t)r * OUTN + c) = lp;
                } else {
                    float2 o;
                    o.x = rw * (1.f / (1.f + expf(-v0)));
                    o.y = rw * (1.f / (1.f + expf(-v1)));
                    *(float2*)(g_eo + (size_t)r * PO + c) = o;
                }
            }
        }
    }
}

__global__ void combine_kernel(float* __restrict__ out) {
    int i = blockIdx.x * blockDim.x + threadIdx.x;
    if (i >= PN * PO) return;
    int n = i >> 10;
    int o = i & (PO - 1);
    int r0 = g_tokrow[n * 2 + 0];
    int r1 = g_tokrow[n * 2 + 1];
    out[i] = g_eo[(size_t)r0 * PO + o] + g_eo[(size_t)r1 * PO + o] +
             g_eo[(size_t)(PNK + n) * PO + o];
}

// ----------------------------------------------------------------------------
// Launch
// ----------------------------------------------------------------------------
extern "C" void kernel_launch(void* const* d_in, const int* in_sizes, int n_in,
                              void* d_out, int out_size) {
    const float* x   = (const float*)d_in[0];
    const float* Wg  = (const float*)d_in[1];
    const float* W1  = (const float*)d_in[2];
    const float* b1  = (const float*)d_in[3];
    const float* g1  = (const float*)d_in[4];
    const float* be1 = (const float*)d_in[5];
    const float* m1  = (const float*)d_in[6];
    const float* v1  = (const float*)d_in[7];
    const float* W2  = (const float*)d_in[8];
    const float* b2  = (const float*)d_in[9];
    const float* g2  = (const float*)d_in[10];
    const float* be2 = (const float*)d_in[11];
    const float* m2  = (const float*)d_in[12];
    const float* v2  = (const float*)d_in[13];
    const float* W3  = (const float*)d_in[14];
    const float* b3  = (const float*)d_in[15];
    const float* sW1 = (const float*)d_in[16];
    const float* sb1 = (const float*)d_in[17];
    const float* sg1 = (const float*)d_in[18];
    const float* sbe1= (const float*)d_in[19];
    const float* sm1 = (const float*)d_in[20];
    const float* sv1 = (const float*)d_in[21];
    const float* sW2 = (const float*)d_in[22];
    const float* sb2 = (const float*)d_in[23];
    const float* sg2 = (const float*)d_in[24];
    const float* sbe2= (const float*)d_in[25];
    const float* sm2 = (const float*)d_in[26];
    const float* sv2 = (const float*)d_in[27];
    const float* sW3 = (const float*)d_in[28];
    const float* sb3 = (const float*)d_in[29];
    float* out = (float*)d_out;

    static int smem_set = 0;
    if (!smem_set) {
        cudaFuncSetAttribute(gemm_mma<PD, 1, PH>,
                             cudaFuncAttributeMaxDynamicSharedMemorySize, SMEM_GEMM);
        cudaFuncSetAttribute(gemm_mma<PH, 2, PH>,
                             cudaFuncAttributeMaxDynamicSharedMemorySize, SMEM_GEMM);
        cudaFuncSetAttribute(gemm_mma<PH, 3, PO>,
                             cudaFuncAttributeMaxDynamicSharedMemorySize, SMEM_GEMM);
        smem_set = 1;
    }

    init_kernel<<<1, 32>>>();
    prep_bn_kernel<<<(PE * PH + 255) / 256, 256>>>(
        g1, be1, m1, v1, g2, be2, m2, v2,
        sg1, sbe1, sm1, sv1, sg2, sbe2, sm2, sv2);
    gate_kernel<<<(PN * 32) / 256, 256>>>(x, Wg);
    scan_kernel<<<1, 32>>>();
    scatter_kernel<<<(PN + 255) / 256, 256>>>();

    {
        __nv_bfloat16 *w1h, *w1l, *w2h, *w2l, *w3h, *w3l;
        __nv_bfloat16 *s1h, *s1l, *s2h, *s2l, *s3h, *s3l;
        cudaGetSymbolAddress((void**)&w1h, g_W1hi); cudaGetSymbolAddress((void**)&w1l, g_W1lo);
        cudaGetSymbolAddress((void**)&w2h, g_W2hi); cudaGetSymbolAddress((void**)&w2l, g_W2lo);
        cudaGetSymbolAddress((void**)&w3h, g_W3hi); cudaGetSymbolAddress((void**)&w3l, g_W3lo);
        cudaGetSymbolAddress((void**)&s1h, g_sW1hi); cudaGetSymbolAddress((void**)&s1l, g_sW1lo);
        cudaGetSymbolAddress((void**)&s2h, g_sW2hi); cudaGetSymbolAddress((void**)&s2l, g_sW2lo);
        cudaGetSymbolAddress((void**)&s3h, g_sW3hi); cudaGetSymbolAddress((void**)&s3l, g_sW3lo);
        int n1 = PE * PH * PD, n2 = PE * PH * PH, n3 = PE * PO * PH;
        conv_split<<<(n1 + 255) / 256, 256>>>(W1, w1h, w1l, n1);
        conv_split<<<(n2 + 255) / 256, 256>>>(W2, w2h, w2l, n2);
        conv_split<<<(n3 + 255) / 256, 256>>>(W3, w3h, w3l, n3);
        conv_split<<<(PH * PD + 255) / 256, 256>>>(sW1, s1h, s1l, PH * PD);
        conv_split<<<(PH * PH + 255) / 256, 256>>>(sW2, s2h, s2l, PH * PH);
        conv_split<<<(PO * PH + 255) / 256, 256>>>(sW3, s3h, s3l, PO * PH);
    }

    gather_x_kernel<<<PROWS, 256>>>(x);

    dim3 grid12(PN / 128, PH / 128, PE + 1);   // (64, 16, 9)
    dim3 grid3(PN / 128, PO / 128, PE + 1);    // (64, 8, 9)
    gemm_mma<PD, 1, PH><<<grid12, 256, SMEM_GEMM>>>(b1, sb1);
    gemm_mma<PH, 2, PH><<<grid12, 256, SMEM_GEMM>>>(b2, sb2);
    gemm_mma<PH, 3, PO><<<grid3, 256, SMEM_GEMM>>>(b3, sb3);

    combine_kernel<<<(PN * PO + 255) / 256, 256>>>(out);
}

// round 8
// speedup vs baseline: 4.7131x; 2.2567x over previous
#include <cuda_runtime.h>
#include <cuda_fp16.h>
#include <math.h>
#include <stdint.h>

// Problem constants
#define PN 8192
#define PD 1024
#define PH 2048
#define PO 1024
#define PE 8
#define PK 2
#define PNK (PN * PK)
#define PROWS (PNK + PN)
#define EPSV 1e-5f

// ----------------------------------------------------------------------------
// Device scratch
// ----------------------------------------------------------------------------
__device__ int   g_count[PE];
__device__ int   g_cursor[PE];
__device__ int   g_segstart[PE + 2];
__device__ int   g_top_e[PN * PK];
__device__ float g_top_w[PN * PK];
__device__ int   g_rowtok[PNK];
__device__ float g_roww[PNK];
__device__ int   g_tokrow[PN * PK];

__device__ float g_a1[PE * PH], g_c1[PE * PH];
__device__ float g_a2[PE * PH], g_c2[PE * PH];
__device__ float g_sa1[PH], g_sc1[PH], g_sa2[PH], g_sc2[PH];

// fp16 weights
__device__ __half g_W1h[(size_t)PE * PH * PD];
__device__ __half g_W2h[(size_t)PE * PH * PH];
__device__ __half g_W3h[(size_t)PE * PO * PH];
__device__ __half g_sW1h[(size_t)PH * PD];
__device__ __half g_sW2h[(size_t)PH * PH];
__device__ __half g_sW3h[(size_t)PO * PH];

// fp16 activations
__device__ __half g_xh[(size_t)PROWS * PD];
__device__ __half g_h1[(size_t)PROWS * PH];
__device__ __half g_h2[(size_t)PROWS * PH];
__device__ float  g_eo[(size_t)PROWS * PO];

// ----------------------------------------------------------------------------
// PTX helpers (base sm_103 target: cp.async, ldmatrix, mma.sync)
// ----------------------------------------------------------------------------
__device__ __forceinline__ uint32_t s2u(const void* p) {
    uint32_t a;
    asm("{ .reg .u64 t; cvta.to.shared.u64 t, %1; cvt.u32.u64 %0, t; }"
        : "=r"(a) : "l"(p));
    return a;
}
__device__ __forceinline__ void cp16(uint32_t d, const void* s) {
    asm volatile("cp.async.cg.shared.global [%0], [%1], 16;" :: "r"(d), "l"(s));
}
__device__ __forceinline__ void cp_commit() { asm volatile("cp.async.commit_group;"); }
__device__ __forceinline__ void cp_wait1()  { asm volatile("cp.async.wait_group 1;"); }
__device__ __forceinline__ void cp_wait0()  { asm volatile("cp.async.wait_group 0;"); }

__device__ __forceinline__ void ldm4(uint32_t* r, uint32_t addr) {
    asm volatile("ldmatrix.sync.aligned.m8n8.x4.shared.b16 {%0,%1,%2,%3}, [%4];"
                 : "=r"(r[0]), "=r"(r[1]), "=r"(r[2]), "=r"(r[3]) : "r"(addr));
}
__device__ __forceinline__ void mma_f16(float* d, const uint32_t* a, const uint32_t* b) {
    asm volatile(
        "mma.sync.aligned.m16n8k16.row.col.f32.f16.f16.f32 "
        "{%0,%1,%2,%3}, {%4,%5,%6,%7}, {%8,%9}, {%0,%1,%2,%3};"
        : "+f"(d[0]), "+f"(d[1]), "+f"(d[2]), "+f"(d[3])
        : "r"(a[0]), "r"(a[1]), "r"(a[2]), "r"(a[3]), "r"(b[0]), "r"(b[1]));
}

// ----------------------------------------------------------------------------
// Routing / prep kernels (verified)
// ----------------------------------------------------------------------------
__global__ void init_kernel() {
    if (threadIdx.x < PE) g_count[threadIdx.x] = 0;
}

__global__ void gate_kernel(const float* __restrict__ x, const float* __restrict__ Wg) {
    int gwarp = (blockIdx.x * blockDim.x + threadIdx.x) >> 5;
    int lane = threadIdx.x & 31;
    if (gwarp >= PN) return;
    const float* xr = x + (size_t)gwarp * PD;
    double logit[PE];
#pragma unroll
    for (int e = 0; e < PE; e++) {
        const float* wr = Wg + (size_t)e * PD;
        double s = 0.0;
        for (int k = lane; k < PD; k += 32) s += (double)xr[k] * (double)wr[k];
#pragma unroll
        for (int off = 16; off; off >>= 1) s += __shfl_down_sync(0xffffffffu, s, off);
        logit[e] = s;
    }
    if (lane == 0) {
        double mx = logit[0];
#pragma unroll
        for (int e = 1; e < PE; e++) if (logit[e] > mx) mx = logit[e];
        double p[PE];
        double psum = 0.0;
#pragma unroll
        for (int e = 0; e < PE; e++) { p[e] = exp(logit[e] - mx); psum += p[e]; }
#pragma unroll
        for (int e = 0; e < PE; e++) p[e] /= psum;
        int i1 = 0;
#pragma unroll
        for (int e = 1; e < PE; e++) if (p[e] > p[i1]) i1 = e;
        int i2 = (i1 == 0) ? 1 : 0;
#pragma unroll
        for (int e = 0; e < PE; e++) if (e != i1 && p[e] > p[i2]) i2 = e;
        float w1 = (float)p[i1], w2 = (float)p[i2];
        float t = w1 + w2 + 1e-20f;
        g_top_e[gwarp * 2 + 0] = i1; g_top_w[gwarp * 2 + 0] = w1 / t;
        g_top_e[gwarp * 2 + 1] = i2; g_top_w[gwarp * 2 + 1] = w2 / t;
        atomicAdd(&g_count[i1], 1);
        atomicAdd(&g_count[i2], 1);
    }
}

__global__ void scan_kernel() {
    if (threadIdx.x == 0 && blockIdx.x == 0) {
        int s = 0;
        for (int e = 0; e < PE; e++) {
            g_segstart[e] = s;
            g_cursor[e] = s;
            s += g_count[e];
        }
        g_segstart[PE] = PNK;
        g_segstart[PE + 1] = PROWS;
    }
}

__global__ void scatter_kernel() {
    int n = blockIdx.x * blockDim.x + threadIdx.x;
    if (n >= PN) return;
#pragma unroll
    for (int j = 0; j < PK; j++) {
        int e = g_top_e[n * PK + j];
        int pos = atomicAdd(&g_cursor[e], 1);
        g_rowtok[pos] = n;
        g_roww[pos] = g_top_w[n * PK + j];
        g_tokrow[n * PK + j] = pos;
    }
}

__global__ void prep_bn_kernel(
    const float* __restrict__ g1, const float* __restrict__ be1,
    const float* __restrict__ m1, const float* __restrict__ v1,
    const float* __restrict__ g2, const float* __restrict__ be2,
    const float* __restrict__ m2, const float* __restrict__ v2,
    const float* __restrict__ sg1, const float* __restrict__ sbe1,
    const float* __restrict__ sm1, const float* __restrict__ sv1,
    const float* __restrict__ sg2, const float* __restrict__ sbe2,
    const float* __restrict__ sm2, const float* __restrict__ sv2) {
    int i = blockIdx.x * blockDim.x + threadIdx.x;
    if (i < PE * PH) {
        float a1v = g1[i] * rsqrtf(v1[i] + EPSV);
        g_a1[i] = a1v; g_c1[i] = be1[i] - m1[i] * a1v;
        float a2v = g2[i] * rsqrtf(v2[i] + EPSV);
        g_a2[i] = a2v; g_c2[i] = be2[i] - m2[i] * a2v;
    }
    if (i < PH) {
        float a1v = sg1[i] * rsqrtf(sv1[i] + EPSV);
        g_sa1[i] = a1v; g_sc1[i] = sbe1[i] - sm1[i] * a1v;
        float a2v = sg2[i] * rsqrtf(sv2[i] + EPSV);
        g_sa2[i] = a2v; g_sc2[i] = sbe2[i] - sm2[i] * a2v;
    }
}

__global__ void conv_half(const float* __restrict__ s, __half* __restrict__ d, int n) {
    int i = blockIdx.x * 256 + threadIdx.x;
    if (i < n) d[i] = __float2half(s[i]);
}

__global__ void gather_x_kernel(const float* __restrict__ x) {
    int row = blockIdx.x;
    int tok = (row < PNK) ? g_rowtok[row] : (row - PNK);
    const float* xr = x + (size_t)tok * PD;
    size_t o = (size_t)row * PD;
    for (int k = threadIdx.x; k < PD; k += 256)
        g_xh[o + k] = __float2half(xr[k]);
}

// ----------------------------------------------------------------------------
// mma.sync fp16 GEMM.  BM=128, BN=128, BK=32, 8 warps (4M x 2N),
// warp tile 32x64.  3-stage cp.async pipeline, 2 CTAs/SM.
// SMEM per stage: {A, B}, each 128 rows x 80 B stride = 10240 B -> 20480/stage.
// ----------------------------------------------------------------------------
#define SROWB 80
#define BUFB  10240
#define STGB  20480
#define NSTG  3
#define SMEM_GEMM (NSTG * STGB)

template <int KDIM, int LAYER, int OUTN>
__global__ __launch_bounds__(256, 2) void gemm_mma(
    const float* __restrict__ bias_r, const float* __restrict__ bias_s) {
    extern __shared__ char smem[];
    const int seg = blockIdx.z;
    const int mbeg = g_segstart[seg], mend = g_segstart[seg + 1];
    const int m0 = mbeg + (int)blockIdx.x * 128;
    if (m0 >= mend) return;
    const int n0 = (int)blockIdx.y * 128;
    const int tid = threadIdx.x;
    const int lane = tid & 31, wid = tid >> 5;
    const int warp_m = wid >> 1, warp_n = wid & 1;   // 4 x 2
    const int mrows = min(128, mend - m0);

    const uint32_t sb = s2u(smem);

    const __half *A, *B;
    if (LAYER == 1) {
        A = g_xh;
        B = (seg < PE) ? g_W1h + (size_t)seg * PH * PD : g_sW1h;
    } else if (LAYER == 2) {
        A = g_h1;
        B = (seg < PE) ? g_W2h + (size_t)seg * PH * PH : g_sW2h;
    } else {
        A = g_h2;
        B = (seg < PE) ? g_W3h + (size_t)seg * PO * PH : g_sW3h;
    }

    auto load_stage = [&](int kk, int st) {
        const uint32_t base = sb + (uint32_t)st * STGB;
#pragma unroll
        for (int j = 0; j < 4; j++) {
            int c = tid + 256 * j;
            int buf = c >> 9;          // 0:A 1:B
            int idx = c & 511;
            int row = idx >> 2;
            int u = idx & 3;
            const __half* src;
            if (buf == 0) {
                int ra = min(row, mrows - 1);
                src = A + (size_t)(m0 + ra) * KDIM + kk + u * 8;
            } else {
                src = B + (size_t)(n0 + row) * KDIM + kk + u * 8;
            }
            cp16(base + (uint32_t)(buf * BUFB + row * SROWB + u * 16), src);
        }
        cp_commit();
    };

    float acc[2][8][4];
#pragma unroll
    for (int i = 0; i < 2; i++)
#pragma unroll
        for (int j = 0; j < 8; j++)
#pragma unroll
            for (int q = 0; q < 4; q++) acc[i][j][q] = 0.f;

    constexpr int NIT = KDIM / 32;
    load_stage(0, 0);
    load_stage(32, 1);

    const int lm = lane >> 3;       // ldmatrix matrix index 0..3
    const int lr = lane & 7;        // row within 8x8

    for (int it = 0; it < NIT; it++) {
        if (it + 1 < NIT) cp_wait1(); else cp_wait0();
        __syncthreads();
        if (it + 2 < NIT) load_stage((it + 2) * 32, (it + 2) % NSTG);

        const uint32_t st = sb + (uint32_t)(it % NSTG) * STGB;

#pragma unroll
        for (int ks = 0; ks < 32; ks += 16) {
            uint32_t ah[2][4];
#pragma unroll
            for (int mt = 0; mt < 2; mt++) {
                int r = warp_m * 32 + mt * 16 + lr + (lm & 1) * 8;
                int cc = ks + (lm >> 1) * 8;
                ldm4(ah[mt], st + (uint32_t)(r * SROWB + cc * 2));
            }
            uint32_t bh[8][2];
#pragma unroll
            for (int np = 0; np < 4; np++) {
                int r = warp_n * 64 + np * 16 + lr + (lm >> 1) * 8;
                int cc = ks + (lm & 1) * 8;
                uint32_t t4[4];
                ldm4(t4, st + (uint32_t)(BUFB + r * SROWB + cc * 2));
                bh[2 * np][0] = t4[0]; bh[2 * np][1] = t4[1];
                bh[2 * np + 1][0] = t4[2]; bh[2 * np + 1][1] = t4[3];
            }
#pragma unroll
            for (int nt = 0; nt < 8; nt++) mma_f16(acc[0][nt], ah[0], bh[nt]);
#pragma unroll
            for (int nt = 0; nt < 8; nt++) mma_f16(acc[1][nt], ah[1], bh[nt]);
        }
    }

    // ------------------------------------------------------------------
    // Epilogue
    // ------------------------------------------------------------------
    const int tr = lane >> 2, tc = (lane & 3) * 2;
    const float* bias;
    const float* bna = nullptr;
    const float* bnc = nullptr;
    if (LAYER == 1) {
        bias = (seg < PE) ? bias_r + (size_t)seg * PH : bias_s;
        bna  = (seg < PE) ? g_a1 + (size_t)seg * PH : g_sa1;
        bnc  = (seg < PE) ? g_c1 + (size_t)seg * PH : g_sc1;
    } else if (LAYER == 2) {
        bias = (seg < PE) ? bias_r + (size_t)seg * PH : bias_s;
        bna  = (seg < PE) ? g_a2 + (size_t)seg * PH : g_sa2;
        bnc  = (seg < PE) ? g_c2 + (size_t)seg * PH : g_sc2;
    } else {
        bias = (seg < PE) ? bias_r + (size_t)seg * PO : bias_s;
    }

    __half* H = (LAYER == 1) ? g_h1 : g_h2;

#pragma unroll
    for (int mt = 0; mt < 2; mt++) {
#pragma unroll
        for (int half = 0; half < 2; half++) {
            int rl = warp_m * 32 + mt * 16 + tr + half * 8;
            if (rl >= mrows) continue;
            int r = m0 + rl;
            float rw = 1.f;
            if (LAYER == 3 && seg < PE) rw = g_roww[r];
#pragma unroll
            for (int nt = 0; nt < 8; nt++) {
                int c = n0 + warp_n * 64 + nt * 8 + tc;
                float v0 = acc[mt][nt][half * 2 + 0] + bias[c];
                float v1 = acc[mt][nt][half * 2 + 1] + bias[c + 1];
                if (LAYER < 3) {
                    v0 = bna[c] * fmaxf(v0, 0.f) + bnc[c];
                    v1 = bna[c + 1] * fmaxf(v1, 0.f) + bnc[c + 1];
                    __half2 hp;
                    hp.x = __float2half(v0);
                    hp.y = __float2half(v1);
                    *(__half2*)(H + (size_t)r * OUTN + c) = hp;
                } else {
                    float2 o;
                    o.x = rw * (1.f / (1.f + expf(-v0)));
                    o.y = rw * (1.f / (1.f + expf(-v1)));
                    *(float2*)(g_eo + (size_t)r * PO + c) = o;
                }
            }
        }
    }
}

__global__ void combine_kernel(float* __restrict__ out) {
    int i = blockIdx.x * blockDim.x + threadIdx.x;
    if (i >= PN * PO) return;
    int n = i >> 10;
    int o = i & (PO - 1);
    int r0 = g_tokrow[n * 2 + 0];
    int r1 = g_tokrow[n * 2 + 1];
    out[i] = g_eo[(size_t)r0 * PO + o] + g_eo[(size_t)r1 * PO + o] +
             g_eo[(size_t)(PNK + n) * PO + o];
}

// ----------------------------------------------------------------------------
// Launch
// ----------------------------------------------------------------------------
extern "C" void kernel_launch(void* const* d_in, const int* in_sizes, int n_in,
                              void* d_out, int out_size) {
    const float* x   = (const float*)d_in[0];
    const float* Wg  = (const float*)d_in[1];
    const float* W1  = (const float*)d_in[2];
    const float* b1  = (const float*)d_in[3];
    const float* g1  = (const float*)d_in[4];
    const float* be1 = (const float*)d_in[5];
    const float* m1  = (const float*)d_in[6];
    const float* v1  = (const float*)d_in[7];
    const float* W2  = (const float*)d_in[8];
    const float* b2  = (const float*)d_in[9];
    const float* g2  = (const float*)d_in[10];
    const float* be2 = (const float*)d_in[11];
    const float* m2  = (const float*)d_in[12];
    const float* v2  = (const float*)d_in[13];
    const float* W3  = (const float*)d_in[14];
    const float* b3  = (const float*)d_in[15];
    const float* sW1 = (const float*)d_in[16];
    const float* sb1 = (const float*)d_in[17];
    const float* sg1 = (const float*)d_in[18];
    const float* sbe1= (const float*)d_in[19];
    const float* sm1 = (const float*)d_in[20];
    const float* sv1 = (const float*)d_in[21];
    const float* sW2 = (const float*)d_in[22];
    const float* sb2 = (const float*)d_in[23];
    const float* sg2 = (const float*)d_in[24];
    const float* sbe2= (const float*)d_in[25];
    const float* sm2 = (const float*)d_in[26];
    const float* sv2 = (const float*)d_in[27];
    const float* sW3 = (const float*)d_in[28];
    const float* sb3 = (const float*)d_in[29];
    float* out = (float*)d_out;

    static int smem_set = 0;
    if (!smem_set) {
        cudaFuncSetAttribute(gemm_mma<PD, 1, PH>,
                             cudaFuncAttributeMaxDynamicSharedMemorySize, SMEM_GEMM);
        cudaFuncSetAttribute(gemm_mma<PH, 2, PH>,
                             cudaFuncAttributeMaxDynamicSharedMemorySize, SMEM_GEMM);
        cudaFuncSetAttribute(gemm_mma<PH, 3, PO>,
                             cudaFuncAttributeMaxDynamicSharedMemorySize, SMEM_GEMM);
        smem_set = 1;
    }

    init_kernel<<<1, 32>>>();
    prep_bn_kernel<<<(PE * PH + 255) / 256, 256>>>(
        g1, be1, m1, v1, g2, be2, m2, v2,
        sg1, sbe1, sm1, sv1, sg2, sbe2, sm2, sv2);
    gate_kernel<<<(PN * 32) / 256, 256>>>(x, Wg);
    scan_kernel<<<1, 32>>>();
    scatter_kernel<<<(PN + 255) / 256, 256>>>();

    {
        __half *w1h, *w2h, *w3h, *s1h, *s2h, *s3h;
        cudaGetSymbolAddress((void**)&w1h, g_W1h);
        cudaGetSymbolAddress((void**)&w2h, g_W2h);
        cudaGetSymbolAddress((void**)&w3h, g_W3h);
        cudaGetSymbolAddress((void**)&s1h, g_sW1h);
        cudaGetSymbolAddress((void**)&s2h, g_sW2h);
        cudaGetSymbolAddress((void**)&s3h, g_sW3h);
        int n1 = PE * PH * PD, n2 = PE * PH * PH, n3 = PE * PO * PH;
        conv_half<<<(n1 + 255) / 256, 256>>>(W1, w1h, n1);
        conv_half<<<(n2 + 255) / 256, 256>>>(W2, w2h, n2);
        conv_half<<<(n3 + 255) / 256, 256>>>(W3, w3h, n3);
        conv_half<<<(PH * PD + 255) / 256, 256>>>(sW1, s1h, PH * PD);
        conv_half<<<(PH * PH + 255) / 256, 256>>>(sW2, s2h, PH * PH);
        conv_half<<<(PO * PH + 255) / 256, 256>>>(sW3, s3h, PO * PH);
    }

    gather_x_kernel<<<PROWS, 256>>>(x);

    dim3 grid12(PN / 128, PH / 128, PE + 1);   // (64, 16, 9)
    dim3 grid3(PN / 128, PO / 128, PE + 1);    // (64, 8, 9)
    gemm_mma<PD, 1, PH><<<grid12, 256, SMEM_GEMM>>>(b1, sb1);
    gemm_mma<PH, 2, PH><<<grid12, 256, SMEM_GEMM>>>(b2, sb2);
    gemm_mma<PH, 3, PO><<<grid3, 256, SMEM_GEMM>>>(b3, sb3);

    combine_kernel<<<(PN * PO + 255) / 256, 256>>>(out);
}